// round 6
// baseline (speedup 1.0000x reference)
#include <cuda_runtime.h>

// ---------------------------------------------------------------------------
// BilateralDenoiser: 15x15 cross-bilateral filter (SIGMA=1 -> N=7, 225 taps)
// input  (1,1080,1920,11) f32:  col=ch0:3  nrm=ch3:6  z=ch9  dz=ch10
// output (1,1080,1920,3)  f32:  sum(col_t * w) / max(sum(w), 1e-4)
//   w = exp(-d^2/2) * clip(nrm_t . nrm_c, 1e-4, 1)^128
//       * exp(-|z_t - z_c| / max(dz_c * d, 1e-4)),  zero outside image.
// Strategy: repack to float4 SoA, SMEM-tile, f32x2 packed math (FFMA2),
//           fold exp(-d^2/2) into the EX2 argument via a per-(dy,dx) table.
// R3 fix: weight table has 300 entries but CTA has 256 threads -> entries
//         256..299 (s=17..19, incl. the valid dy=+7 row of center 1) were
//         uninitialized smem. Grid-stride the init loop.
// ---------------------------------------------------------------------------

#define IH 1080
#define IW 1920
#define ICH 11
#define TILE 32
#define SWID 46          // TILE + 2*7
#define NROWS 18         // PY + 14, PY = 4
#define TABN (20 * 15)   // 300 entries: s in [0,19], dx in [0,14]
#define FEPS 1e-4f

__device__ float4 g_A[IH * IW];  // nrm.x, nrm.y, nrm.z, z
__device__ float4 g_B[IH * IW];  // col.r, col.g, col.b, dz

// ---------------- f32x2 helpers (Blackwell packed fp32) ---------------------
__device__ __forceinline__ unsigned long long pk(float lo, float hi) {
    unsigned long long r;
    asm("mov.b64 %0, {%1, %2};" : "=l"(r)
        : "r"(__float_as_uint(lo)), "r"(__float_as_uint(hi)));
    return r;
}
__device__ __forceinline__ void upk(unsigned long long v, float& lo, float& hi) {
    unsigned int a, b;
    asm("mov.b64 {%0, %1}, %2;" : "=r"(a), "=r"(b) : "l"(v));
    lo = __uint_as_float(a); hi = __uint_as_float(b);
}
__device__ __forceinline__ unsigned long long f2mul(unsigned long long a, unsigned long long b) {
    unsigned long long d;
    asm("mul.rn.f32x2 %0, %1, %2;" : "=l"(d) : "l"(a), "l"(b));
    return d;
}
__device__ __forceinline__ unsigned long long f2add(unsigned long long a, unsigned long long b) {
    unsigned long long d;
    asm("add.rn.f32x2 %0, %1, %2;" : "=l"(d) : "l"(a), "l"(b));
    return d;
}
__device__ __forceinline__ unsigned long long f2fma(unsigned long long a, unsigned long long b,
                                                    unsigned long long c) {
    unsigned long long d;
    asm("fma.rn.f32x2 %0, %1, %2, %3;" : "=l"(d) : "l"(a), "l"(b), "l"(c));
    return d;
}
__device__ __forceinline__ float rcpa(float x) {
    float y; asm("rcp.approx.f32 %0, %1;" : "=f"(y) : "f"(x)); return y;
}
__device__ __forceinline__ float ex2a(float x) {
    float y; asm("ex2.approx.f32 %0, %1;" : "=f"(y) : "f"(x)); return y;
}

// ---------------- repack: AoS(11ch) -> two float4 SoA buffers ----------------
__global__ void repack_kernel(const float* __restrict__ in) {
    int i = blockIdx.x * blockDim.x + threadIdx.x;
    if (i >= IH * IW) return;
    const float* p = in + (size_t)i * ICH;
    g_A[i] = make_float4(p[3], p[4], p[5], p[9]);
    g_B[i] = make_float4(p[0], p[1], p[2], p[10]);
}

// ---------------- one packed pair (2 centers) for one neighbor pixel --------
__device__ __forceinline__ void tap_pair(
    unsigned long long ax2, unsigned long long ay2, unsigned long long az2,
    unsigned long long zn2,
    unsigned long long cr2, unsigned long long cg2, unsigned long long cb2,
    unsigned long long cnx2, unsigned long long cny2, unsigned long long cnz2,
    unsigned long long ncz2, unsigned long long cdz2,
    unsigned long long cxy2, unsigned long long dist2, unsigned long long nl2e2,
    unsigned long long& ar, unsigned long long& ag, unsigned long long& ab,
    unsigned long long& aw)
{
    // dot(nrm_t, nrm_c), clamp [eps,1], ^128 via 7 squarings
    unsigned long long dot2 = f2fma(az2, cnz2, f2fma(ay2, cny2, f2mul(ax2, cnx2)));
    float d0, d1; upk(dot2, d0, d1);
    d0 = fminf(fmaxf(d0, FEPS), 1.0f);
    d1 = fminf(fmaxf(d1, FEPS), 1.0f);
    unsigned long long s2 = pk(d0, d1);
    s2 = f2mul(s2, s2); s2 = f2mul(s2, s2); s2 = f2mul(s2, s2); s2 = f2mul(s2, s2);
    s2 = f2mul(s2, s2); s2 = f2mul(s2, s2); s2 = f2mul(s2, s2);       // ^128

    // depth term: exp2(-|zt-zc| / max(dz*d,eps) * log2e + cxy)  (w_xy folded in)
    unsigned long long zd2 = f2add(zn2, ncz2) & 0x7FFFFFFF7FFFFFFFull; // |zt-zc|
    unsigned long long den2 = f2mul(cdz2, dist2);
    float e0, e1; upk(den2, e0, e1);
    float r0 = rcpa(fmaxf(e0, FEPS));
    float r1 = rcpa(fmaxf(e1, FEPS));
    unsigned long long t2  = f2mul(zd2, pk(r0, r1));
    unsigned long long arg = f2fma(t2, nl2e2, cxy2);
    float q0, q1; upk(arg, q0, q1);
    unsigned long long wd2 = pk(ex2a(q0), ex2a(q1));

    unsigned long long w2 = f2mul(s2, wd2);
    aw = f2add(aw, w2);
    ar = f2fma(cr2, w2, ar);
    ag = f2fma(cg2, w2, ag);
    ab = f2fma(cb2, w2, ab);
}

// ---------------- main tiled kernel: 32x32 outputs / CTA, PY=4 per thread ---
__global__ void __launch_bounds__(256)
bilateral_kernel(float* __restrict__ out) {
    extern __shared__ unsigned char smraw[];
    float4*     sA   = reinterpret_cast<float4*>(smraw);
    float4*     sB   = sA + SWID * SWID;
    ulonglong2* sTab = reinterpret_cast<ulonglong2*>(sB + SWID * SWID);

    const int tix  = threadIdx.x;
    const int tidy = threadIdx.y;
    const int tid  = tidy * 32 + tix;
    const int gx0  = blockIdx.x * TILE - 7;
    const int gy0  = blockIdx.y * TILE - 7;

    // fill 46x46 halo tile; OOB pixels -> zeros (nrm=0 => weight exactly 0)
    for (int i = tid; i < SWID * SWID; i += 256) {
        int ly = i / SWID, lx = i - ly * SWID;
        int gy = gy0 + ly, gx = gx0 + lx;
        float4 a = make_float4(0.f, 0.f, 0.f, 0.f);
        float4 b = a;
        if ((unsigned)gy < (unsigned)IH && (unsigned)gx < (unsigned)IW) {
            int g = gy * IW + gx;
            a = g_A[g]; b = g_B[g];
        }
        sA[i] = a; sB[i] = b;
    }
    // per-(dy,dx) table: entry s holds halves (dyA=s-9, dyB=s-10) for one dx.
    // cxy = -(dy^2+dx^2)*log2e/2 (or -1e30 => weight 0 when |dy|>7), dist = sqrt.
    // R3 FIX: 300 entries > 256 threads -> must grid-stride, not `if (tid<300)`.
    for (int i = tid; i < TABN; i += 256) {
        int s = i / 15, dxi = i - s * 15;
        float dx = (float)(dxi - 7);
        int dyA = s - 9, dyB = s - 10;
        float qA = dyA * dyA + dx * dx, qB = dyB * dyB + dx * dx;
        bool vA = (dyA >= -7) && (dyA <= 7);
        bool vB = (dyB >= -7) && (dyB <= 7);
        float cA = vA ? -qA * 0.72134752044f : -1e30f;
        float cB = vB ? -qB * 0.72134752044f : -1e30f;
        float dA = vA ? sqrtf(qA) : 0.f;
        float dB = vB ? sqrtf(qB) : 0.f;
        sTab[i] = make_ulonglong2(pk(cA, cB), pk(dA, dB));
    }
    __syncthreads();

    // center data for 4 rows (2 packed pairs): pair p = centers (2p, 2p+1)
    const int tidy4 = tidy * 4;
    unsigned long long cnx2[2], cny2[2], cnz2[2], ncz2[2], cdz2[2];
#pragma unroll
    for (int p = 0; p < 2; ++p) {
        int rA = tidy4 + 2 * p + 7;
        float4 aA = sA[rA * SWID + tix + 7];
        float4 aB = sA[(rA + 1) * SWID + tix + 7];
        float dzA = sB[rA * SWID + tix + 7].w;
        float dzB = sB[(rA + 1) * SWID + tix + 7].w;
        cnx2[p] = pk(aA.x, aB.x);
        cny2[p] = pk(aA.y, aB.y);
        cnz2[p] = pk(aA.z, aB.z);
        ncz2[p] = pk(-aA.w, -aB.w);
        cdz2[p] = pk(dzA, dzB);
    }
    unsigned long long ar2[2] = {0ull, 0ull}, ag2[2] = {0ull, 0ull};
    unsigned long long ab2[2] = {0ull, 0ull}, aw2[2] = {0ull, 0ull};
    const unsigned long long NL2E = pk(-1.4426950408889634f, -1.4426950408889634f);

    const int rowbase = tidy4 * SWID + tix;
#pragma unroll 1
    for (int dxi = 0; dxi < 15; ++dxi) {
#pragma unroll 3
        for (int nyi = 0; nyi < NROWS; ++nyi) {
            int idx = rowbase + nyi * SWID + dxi;
            float4 a = sA[idx];
            float4 b = sB[idx];
            unsigned long long ax2 = pk(a.x, a.x), ay2 = pk(a.y, a.y);
            unsigned long long az2 = pk(a.z, a.z), zn2 = pk(a.w, a.w);
            unsigned long long cr2 = pk(b.x, b.x), cg2 = pk(b.y, b.y);
            unsigned long long cb2 = pk(b.z, b.z);
            ulonglong2 T0 = sTab[(nyi + 2) * 15 + dxi];  // pair 0: dy = nyi-7, nyi-8
            ulonglong2 T1 = sTab[nyi * 15 + dxi];        // pair 1: dy = nyi-9, nyi-10
            tap_pair(ax2, ay2, az2, zn2, cr2, cg2, cb2,
                     cnx2[0], cny2[0], cnz2[0], ncz2[0], cdz2[0],
                     T0.x, T0.y, NL2E, ar2[0], ag2[0], ab2[0], aw2[0]);
            tap_pair(ax2, ay2, az2, zn2, cr2, cg2, cb2,
                     cnx2[1], cny2[1], cnz2[1], ncz2[1], cdz2[1],
                     T1.x, T1.y, NL2E, ar2[1], ag2[1], ab2[1], aw2[1]);
        }
    }

    // write out: out[(gy*W+gx)*3 + ch] = acc_col / max(acc_w, eps)
    const int gx  = blockIdx.x * TILE + tix;
    const int gyb = blockIdx.y * TILE + tidy4;
#pragma unroll
    for (int p = 0; p < 2; ++p) {
        float w0, w1, r0, r1, q0, q1, b0, b1;
        upk(aw2[p], w0, w1);
        upk(ar2[p], r0, r1);
        upk(ag2[p], q0, q1);
        upk(ab2[p], b0, b1);
        int gy = gyb + 2 * p;
        if (gy < IH) {
            float inv = rcpa(fmaxf(w0, FEPS));
            float* o = out + ((size_t)gy * IW + gx) * 3;
            o[0] = r0 * inv; o[1] = q0 * inv; o[2] = b0 * inv;
        }
        if (gy + 1 < IH) {
            float inv = rcpa(fmaxf(w1, FEPS));
            float* o = out + ((size_t)(gy + 1) * IW + gx) * 3;
            o[0] = r1 * inv; o[1] = q1 * inv; o[2] = b1 * inv;
        }
    }
}

extern "C" void kernel_launch(void* const* d_in, const int* in_sizes, int n_in,
                              void* d_out, int out_size) {
    (void)in_sizes; (void)n_in; (void)out_size;
    const float* in = (const float*)d_in[0];
    float* out = (float*)d_out;

    repack_kernel<<<(IH * IW + 255) / 256, 256>>>(in);

    const int smem = SWID * SWID * 2 * (int)sizeof(float4) + TABN * (int)sizeof(ulonglong2);
    cudaFuncSetAttribute(bilateral_kernel,
                         cudaFuncAttributeMaxDynamicSharedMemorySize, smem);
    dim3 blk(32, 8);
    dim3 grd(IW / TILE, (IH + TILE - 1) / TILE);
    bilateral_kernel<<<grd, blk, smem>>>(out);
}

// round 10
// speedup vs baseline: 1.4012x; 1.4012x over previous
#include <cuda_runtime.h>

// ---------------------------------------------------------------------------
// BilateralDenoiser: 15x15 cross-bilateral filter (SIGMA=1 -> N=7, 225 taps)
//   w = exp(-d^2/2) * clip(nrm_t . nrm_c, eps, 1)^128
//       * exp(-|z_t - z_c| / max(dz_c * d, eps)),  zero outside image.
// R6: issue-bound (76.8%). Cut instructions:
//   - per-tap rcp -> precomputed rr=log2e/dz (inf if dz<=0) * table 1/dist,
//     clamped with one fmin (1/max(q,eps) == min(1/q, 1e4) for q>0).
//   - s^128 (7 packed muls) -> 128*lg2(s) folded into the single ex2 arg.
//   - scalar dot/clamp/depth chain (no broadcast MOVs); packed f32x2 accums.
// ---------------------------------------------------------------------------

#define IH 1080
#define IW 1920
#define ICH 11
#define TILE 32
#define SWID 46          // TILE + 2*7
#define NROWS 18         // PY + 14, PY = 4
#define TABN (20 * 15)   // 300 entries: s in [0,19], dx in [0,14]
#define FEPS 1e-4f
#define RDEN_CLAMP 14426.950408889634f   // 1e4 * log2(e)
#define F32_INF __int_as_float(0x7f800000)

__device__ float4 g_A[IH * IW];  // nrm.x, nrm.y, nrm.z, z
__device__ float4 g_B[IH * IW];  // col.r, col.g, col.b, rr (= log2e/dz or +inf)

// ---------------- helpers ---------------------------------------------------
__device__ __forceinline__ unsigned long long pk(float lo, float hi) {
    unsigned long long r;
    asm("mov.b64 %0, {%1, %2};" : "=l"(r)
        : "r"(__float_as_uint(lo)), "r"(__float_as_uint(hi)));
    return r;
}
__device__ __forceinline__ void upk(unsigned long long v, float& lo, float& hi) {
    unsigned int a, b;
    asm("mov.b64 {%0, %1}, %2;" : "=r"(a), "=r"(b) : "l"(v));
    lo = __uint_as_float(a); hi = __uint_as_float(b);
}
__device__ __forceinline__ unsigned long long f2add(unsigned long long a, unsigned long long b) {
    unsigned long long d;
    asm("add.rn.f32x2 %0, %1, %2;" : "=l"(d) : "l"(a), "l"(b));
    return d;
}
__device__ __forceinline__ unsigned long long f2fma(unsigned long long a, unsigned long long b,
                                                    unsigned long long c) {
    unsigned long long d;
    asm("fma.rn.f32x2 %0, %1, %2, %3;" : "=l"(d) : "l"(a), "l"(b), "l"(c));
    return d;
}
__device__ __forceinline__ float rcpa(float x) {
    float y; asm("rcp.approx.f32 %0, %1;" : "=f"(y) : "f"(x)); return y;
}
__device__ __forceinline__ float ex2a(float x) {
    float y; asm("ex2.approx.f32 %0, %1;" : "=f"(y) : "f"(x)); return y;
}
__device__ __forceinline__ float lg2a(float x) {
    float y; asm("lg2.approx.f32 %0, %1;" : "=f"(y) : "f"(x)); return y;
}

// ---------------- repack: AoS(11ch) -> two float4 SoA buffers ----------------
__global__ void repack_kernel(const float* __restrict__ in) {
    int i = blockIdx.x * blockDim.x + threadIdx.x;
    if (i >= IH * IW) return;
    const float* p = in + (size_t)i * ICH;
    float dz = p[10];
    float rr = (dz > 0.0f) ? rcpa(dz) * 1.4426950408889634f : F32_INF;
    g_A[i] = make_float4(p[3], p[4], p[5], p[9]);
    g_B[i] = make_float4(p[0], p[1], p[2], rr);
}

// ---------------- main tiled kernel: 32x32 outputs / CTA, PY=4 per thread ---
__global__ void __launch_bounds__(256)
bilateral_kernel(float* __restrict__ out) {
    extern __shared__ unsigned char smraw[];
    float4* sA   = reinterpret_cast<float4*>(smraw);
    float4* sB   = sA + SWID * SWID;
    float4* sTab = sB + SWID * SWID;   // {cxyA, cxyB, rdA, rdB} per (s,dx)

    const int tix  = threadIdx.x;
    const int tidy = threadIdx.y;
    const int tid  = tidy * 32 + tix;
    const int gx0  = blockIdx.x * TILE - 7;
    const int gy0  = blockIdx.y * TILE - 7;

    // fill 46x46 halo tile; OOB pixels -> zeros (nrm=0 => weight exactly 0)
    for (int i = tid; i < SWID * SWID; i += 256) {
        int ly = i / SWID, lx = i - ly * SWID;
        int gy = gy0 + ly, gx = gx0 + lx;
        float4 a = make_float4(0.f, 0.f, 0.f, 0.f);
        float4 b = a;
        if ((unsigned)gy < (unsigned)IH && (unsigned)gx < (unsigned)IW) {
            int g = gy * IW + gx;
            a = g_A[g]; b = g_B[g];
        }
        sA[i] = a; sB[i] = b;
    }
    // per-(dy,dx) table. entry s covers lane pair (dyA=s-9, dyB=s-10).
    //   cxy = -(dy^2+dx^2)*log2e/2   (-1e30 kills weight when |dy|>7)
    //   rd  = 1/dist (inf at dist=0; the fmin clamp absorbs it)
    for (int i = tid; i < TABN; i += 256) {
        int s = i / 15, dxi = i - s * 15;
        float dx = (float)(dxi - 7);
        int dyA = s - 9, dyB = s - 10;
        float qA = dyA * dyA + dx * dx, qB = dyB * dyB + dx * dx;
        bool vA = (dyA >= -7) && (dyA <= 7);
        bool vB = (dyB >= -7) && (dyB <= 7);
        float cA = vA ? -qA * 0.72134752044f : -1e30f;
        float cB = vB ? -qB * 0.72134752044f : -1e30f;
        float rA = vA ? rsqrtf(qA) : 1e4f;   // rsqrt(0) = +inf (center tap)
        float rB = vB ? rsqrtf(qB) : 1e4f;
        sTab[i] = make_float4(cA, cB, rA, rB);
    }
    __syncthreads();

    // center data for 4 rows: c = 0..3 (pair p holds centers 2p, 2p+1)
    const int tidy4 = tidy * 4;
    float cnx[4], cny[4], cnz[4], cz[4], crr[4];
#pragma unroll
    for (int c = 0; c < 4; ++c) {
        int r = tidy4 + c + 7;
        float4 a = sA[r * SWID + tix + 7];
        cnx[c] = a.x; cny[c] = a.y; cnz[c] = a.z; cz[c] = a.w;
        crr[c] = sB[r * SWID + tix + 7].w;
    }
    unsigned long long ar2[2] = {0ull, 0ull}, ag2[2] = {0ull, 0ull};
    unsigned long long ab2[2] = {0ull, 0ull}, aw2[2] = {0ull, 0ull};

    const int rowbase = tidy4 * SWID + tix;
#pragma unroll 1
    for (int dxi = 0; dxi < 15; ++dxi) {
#pragma unroll 3
        for (int nyi = 0; nyi < NROWS; ++nyi) {
            int idx = rowbase + nyi * SWID + dxi;
            float4 a = sA[idx];                 // nx, ny, nz, z
            float4 b = sB[idx];                 // r, g, b, (rr unused)
            unsigned long long cr2 = pk(b.x, b.x);
            unsigned long long cg2 = pk(b.y, b.y);
            unsigned long long cb2 = pk(b.z, b.z);
            float4 T0 = sTab[(nyi + 2) * 15 + dxi];  // pair 0: dy = nyi-7, nyi-8
            float4 T1 = sTab[nyi * 15 + dxi];        // pair 1: dy = nyi-9, nyi-10

            float w[4];
#pragma unroll
            for (int p = 0; p < 2; ++p) {
                const float4& T = p ? T1 : T0;
#pragma unroll
                for (int l = 0; l < 2; ++l) {
                    int c = 2 * p + l;
                    // normal term: 128*lg2(clamp(dot,0,1)); lg2(0)=-inf => w=0
                    float d = fmaf(a.z, cnz[c], fmaf(a.y, cny[c], a.x * cnx[c]));
                    float s = fminf(fmaxf(d, 0.0f), 1.0f);
                    float lg = lg2a(s);
                    // depth term: |z_t - z_c| * min(rr_c * (1/dist), 1e4*log2e)
                    float t    = fabsf(a.w - cz[c]);
                    float rden = fminf(crr[c] * (l ? T.w : T.z), RDEN_CLAMP);
                    // w = exp2( cxy + 128*lg - t*rden )
                    float arg = fmaf(lg, 128.0f, l ? T.y : T.x);
                    arg = fmaf(-t, rden, arg);
                    w[c] = ex2a(arg);
                }
                unsigned long long w2 = pk(w[2 * p], w[2 * p + 1]);
                aw2[p] = f2add(aw2[p], w2);
                ar2[p] = f2fma(cr2, w2, ar2[p]);
                ag2[p] = f2fma(cg2, w2, ag2[p]);
                ab2[p] = f2fma(cb2, w2, ab2[p]);
            }
        }
    }

    // write out: out[(gy*W+gx)*3 + ch] = acc_col / max(acc_w, eps)
    const int gx  = blockIdx.x * TILE + tix;
    const int gyb = blockIdx.y * TILE + tidy4;
#pragma unroll
    for (int p = 0; p < 2; ++p) {
        float w0, w1, r0, r1, q0, q1, b0, b1;
        upk(aw2[p], w0, w1);
        upk(ar2[p], r0, r1);
        upk(ag2[p], q0, q1);
        upk(ab2[p], b0, b1);
        int gy = gyb + 2 * p;
        if (gy < IH) {
            float inv = rcpa(fmaxf(w0, FEPS));
            float* o = out + ((size_t)gy * IW + gx) * 3;
            o[0] = r0 * inv; o[1] = q0 * inv; o[2] = b0 * inv;
        }
        if (gy + 1 < IH) {
            float inv = rcpa(fmaxf(w1, FEPS));
            float* o = out + ((size_t)(gy + 1) * IW + gx) * 3;
            o[0] = r1 * inv; o[1] = q1 * inv; o[2] = b1 * inv;
        }
    }
}

extern "C" void kernel_launch(void* const* d_in, const int* in_sizes, int n_in,
                              void* d_out, int out_size) {
    (void)in_sizes; (void)n_in; (void)out_size;
    const float* in = (const float*)d_in[0];
    float* out = (float*)d_out;

    repack_kernel<<<(IH * IW + 255) / 256, 256>>>(in);

    const int smem = (SWID * SWID * 2 + TABN) * (int)sizeof(float4);
    cudaFuncSetAttribute(bilateral_kernel,
                         cudaFuncAttributeMaxDynamicSharedMemorySize, smem);
    dim3 blk(32, 8);
    dim3 grd(IW / TILE, (IH + TILE - 1) / TILE);
    bilateral_kernel<<<grd, blk, smem>>>(out);
}